// round 8
// baseline (speedup 1.0000x reference)
#include <cuda_runtime.h>
#include <math.h>
#include <stdint.h>

#define NTOK 32768
#define INF  204
#define HD   128
#define NM   4
#define AD   14
#define KD   32
#define TT   64

// uniform weight chunks: 6144 floats (24KB). 5 fc1 chunks (48 K-rows x 128) + 16 gate chunks (16 K-rows x 384)
#define CH_F 6144
#define NCH  21
#define STREAM_F (NCH * CH_F)

// main kernel smem (float offsets)
#define SX 212
#define SH 132
#define OFF_X   0
#define OFF_H   13568
#define OFF_STG 22016
#define OFF_W2  (OFF_STG + 3*CH_F)
#define OFF_AUX (OFF_W2 + 1792)
#define SMEM_MAIN_FLOATS (OFF_AUX + 64)
#define SMEM_MAIN_BYTES  (SMEM_MAIN_FLOATS * 4)
#define SMEM_ROUTER (128 * 129 * 4)

__device__ __align__(16) float g_S[NM * STREAM_F];
__device__ int g_cnt[NM];
__device__ int g_list[NM * NTOK];
__device__ unsigned char g_sel[NTOK];

// ---------------- helpers ----------------
__device__ __forceinline__ uint32_t smem_u32(const void* p) {
    return (uint32_t)__cvta_generic_to_shared(p);
}
__device__ __forceinline__ void cpa16(uint32_t d, const void* s) {
    asm volatile("cp.async.ca.shared.global [%0], [%1], 16;" :: "r"(d), "l"(s));
}
__device__ __forceinline__ void cpa_commit() { asm volatile("cp.async.commit_group;"); }
template<int N> __device__ __forceinline__ void cpa_wait() {
    asm volatile("cp.async.wait_group %0;" :: "n"(N));
}
__device__ __forceinline__ void mma8(float (&d)[4], const uint32_t (&a)[4],
                                     uint32_t b0, uint32_t b1) {
    asm volatile("mma.sync.aligned.m16n8k8.row.col.f32.tf32.tf32.f32 "
        "{%0,%1,%2,%3},{%4,%5,%6,%7},{%8,%9},{%0,%1,%2,%3};"
        : "+f"(d[0]), "+f"(d[1]), "+f"(d[2]), "+f"(d[3])
        : "r"(a[0]), "r"(a[1]), "r"(a[2]), "r"(a[3]), "r"(b0), "r"(b1));
}
__device__ __forceinline__ float sigf(float x) { return 1.f / (1.f + __expf(-x)); }
__device__ __forceinline__ float tanhfast(float x) {
    return 1.f - 2.f / (__expf(2.f * x) + 1.f);
}

// ---------------- merged router + prep ----------------
// blocks 0..255: router (128 tokens, 2 threads/token). blocks 256..339: prep.
__global__ void __launch_bounds__(256) router_prep_kernel(
    const float* __restrict__ hidden,
    const float* __restrict__ w1, const float* __restrict__ b1,
    const float* __restrict__ w2, const float* __restrict__ b2,
    const float* __restrict__ w3, const float* __restrict__ b3,
    const float* __restrict__ wq, const float* __restrict__ bq,
    const float* __restrict__ wk, const float* __restrict__ bk,
    const float* __restrict__ mkeys,
    const float* __restrict__ unif,
    const float* __restrict__ wih, const float* __restrict__ whh,
    const float* __restrict__ fc1w)
{
    const int tid = threadIdx.x;

    if (blockIdx.x >= 256) {
        const int id = blockIdx.x - 256;         // m*21 + ch
        const int m = id / NCH, ch = id - m * NCH;
        float* dst = g_S + (size_t)m * STREAM_F + (size_t)ch * CH_F;
        for (int o = tid; o < CH_F; o += 256) {
            int f = o & 3, q = o >> 2;
            float v;
            if (ch < 5) {                        // fc1: 48 K-rows, [nt16][p3][lane][4]
                int nt = q / 96, r = q - nt * 96, p = r >> 5, l = r & 31;
                int k = 48 * ch + 16 * p + 4 * f + (l & 3);
                int n = 8 * nt + (l >> 2);
                v = (k < INF) ? fc1w[(size_t)m * INF * HD + (size_t)k * HD + n] : 0.f;
            } else {                             // gates: 16 K-rows, [nt48][lane][4]
                int j = ch - 5;
                int nt = q >> 5, l = q & 31;
                int k = 16 * j + 4 * f + (l & 3);
                int n = 8 * nt + (l >> 2);
                v = (k < 128) ? wih[(size_t)m * HD * 384 + (size_t)k * 384 + n]
                              : whh[(size_t)m * HD * 384 + (size_t)(k - 128) * 384 + n];
            }
            uint32_t t32;
            asm("cvt.rna.tf32.f32 %0, %1;" : "=r"(t32) : "f"(v));
            dst[o] = __uint_as_float(t32);
        }
        return;
    }

    // ---- router: 2 threads per token, 16 outputs each, shfl pair-exchange ----
    extern __shared__ float HS[];                // [128][129]
    __shared__ float w1s[HD * KD], w2s[KD * KD], w3s[KD * KD], wqs[KD * KD], kps[NM * KD];

    for (int i = tid; i < HD * KD; i += 256) w1s[i] = w1[i];
    for (int i = tid; i < KD * KD; i += 256) { w2s[i] = w2[i]; w3s[i] = w3[i]; wqs[i] = wq[i]; }
    if (tid < NM * KD) {
        int m = tid / KD, j = tid % KD;
        float acc = bk[j];
        #pragma unroll
        for (int k = 0; k < KD; k++) acc = fmaf(mkeys[m * KD + k], wk[k * KD + j], acc);
        kps[tid] = acc;
    }
    const size_t hb = (size_t)blockIdx.x * 128 * HD;
    for (int i = tid; i < 128 * HD; i += 256) {
        int t = i >> 7, c = i & 127;
        HS[t * 129 + c] = hidden[hb + (size_t)t * HD + c];
    }
    __syncthreads();

    const int t = tid >> 1, half = tid & 1;
    const int tok = blockIdx.x * 128 + t;
    const int cb = half * 16;
    const float* h = &HS[t * 129];

    float q1[16];
    #pragma unroll
    for (int j = 0; j < 16; j++) q1[j] = b1[cb + j];
    for (int k = 0; k < HD; k++) {
        float hk = h[k];
        const float4* wr = (const float4*)(w1s + k * KD + cb);
        #pragma unroll
        for (int j4 = 0; j4 < 4; j4++) {
            float4 wv = wr[j4];
            q1[4*j4+0] = fmaf(hk, wv.x, q1[4*j4+0]);
            q1[4*j4+1] = fmaf(hk, wv.y, q1[4*j4+1]);
            q1[4*j4+2] = fmaf(hk, wv.z, q1[4*j4+2]);
            q1[4*j4+3] = fmaf(hk, wv.w, q1[4*j4+3]);
        }
    }
    #pragma unroll
    for (int j = 0; j < 16; j++) q1[j] = fmaxf(q1[j], 0.f);

    float f1[32];
    #pragma unroll
    for (int j = 0; j < 16; j++) f1[cb + j] = q1[j];
    #pragma unroll
    for (int j = 0; j < 16; j++)
        f1[(16 - cb) + j] = __shfl_xor_sync(0xffffffffu, q1[j], 1);

    float q2[16];
    #pragma unroll
    for (int j = 0; j < 16; j++) q2[j] = b2[cb + j];
    #pragma unroll
    for (int k = 0; k < KD; k++) {
        float a = f1[k];
        const float4* wr = (const float4*)(w2s + k * KD + cb);
        #pragma unroll
        for (int j4 = 0; j4 < 4; j4++) {
            float4 wv = wr[j4];
            q2[4*j4+0] = fmaf(a, wv.x, q2[4*j4+0]);
            q2[4*j4+1] = fmaf(a, wv.y, q2[4*j4+1]);
            q2[4*j4+2] = fmaf(a, wv.z, q2[4*j4+2]);
            q2[4*j4+3] = fmaf(a, wv.w, q2[4*j4+3]);
        }
    }
    #pragma unroll
    for (int j = 0; j < 16; j++) q2[j] = fmaxf(q2[j], 0.f);

    float f2[32];
    #pragma unroll
    for (int j = 0; j < 16; j++) f2[cb + j] = q2[j];
    #pragma unroll
    for (int j = 0; j < 16; j++)
        f2[(16 - cb) + j] = __shfl_xor_sync(0xffffffffu, q2[j], 1);

    float q3[16];
    #pragma unroll
    for (int j = 0; j < 16; j++) q3[j] = b3[cb + j];
    #pragma unroll
    for (int k = 0; k < KD; k++) {
        float a = f2[k];
        const float4* wr = (const float4*)(w3s + k * KD + cb);
        #pragma unroll
        for (int j4 = 0; j4 < 4; j4++) {
            float4 wv = wr[j4];
            q3[4*j4+0] = fmaf(a, wv.x, q3[4*j4+0]);
            q3[4*j4+1] = fmaf(a, wv.y, q3[4*j4+1]);
            q3[4*j4+2] = fmaf(a, wv.z, q3[4*j4+2]);
            q3[4*j4+3] = fmaf(a, wv.w, q3[4*j4+3]);
        }
    }

    float f3[32];
    #pragma unroll
    for (int j = 0; j < 16; j++) f3[cb + j] = q3[j];
    #pragma unroll
    for (int j = 0; j < 16; j++)
        f3[(16 - cb) + j] = __shfl_xor_sync(0xffffffffu, q3[j], 1);

    float q4[16];
    #pragma unroll
    for (int j = 0; j < 16; j++) q4[j] = bq[cb + j];
    #pragma unroll
    for (int k = 0; k < KD; k++) {
        float a = f3[k];
        const float4* wr = (const float4*)(wqs + k * KD + cb);
        #pragma unroll
        for (int j4 = 0; j4 < 4; j4++) {
            float4 wv = wr[j4];
            q4[4*j4+0] = fmaf(a, wv.x, q4[4*j4+0]);
            q4[4*j4+1] = fmaf(a, wv.y, q4[4*j4+1]);
            q4[4*j4+2] = fmaf(a, wv.z, q4[4*j4+2]);
            q4[4*j4+3] = fmaf(a, wv.w, q4[4*j4+3]);
        }
    }

    float qp[32];
    #pragma unroll
    for (int j = 0; j < 16; j++) qp[cb + j] = q4[j];
    #pragma unroll
    for (int j = 0; j < 16; j++)
        qp[(16 - cb) + j] = __shfl_xor_sync(0xffffffffu, q4[j], 1);

    float lg[NM];
    #pragma unroll
    for (int mm = 0; mm < NM; mm++) {
        float a = 0.f;
        #pragma unroll
        for (int j = 0; j < KD; j++) a = fmaf(qp[j], kps[mm * KD + j], a);
        lg[mm] = a * 0.17677669529663687f;
    }
    float mx = fmaxf(fmaxf(lg[0], lg[1]), fmaxf(lg[2], lg[3]));
    float s = 0.f;
    #pragma unroll
    for (int mm = 0; mm < NM; mm++) { lg[mm] = expf(lg[mm] - mx); s += lg[mm]; }
    float inv = 1.f / s;
    float best = -1e30f; int sel = 0;
    #pragma unroll
    for (int mm = 0; mm < NM; mm++) {
        float u = unif[(size_t)tok * NM + mm];
        float g = -logf(-logf(u + 1e-10f) + 1e-10f);
        float y = fmaf(lg[mm], inv, g);
        if (y > best) { best = y; sel = mm; }
    }
    if (half == 0) g_sel[tok] = (unsigned char)sel;
}

// ---------------- compact (deterministic, 1 block) ----------------
__global__ void __launch_bounds__(1024) compact_kernel() {
    __shared__ int scnt[NM * 1024];
    const int tid = threadIdx.x;
    const int t0 = tid * 32;
    unsigned char sel[32];
    int c0 = 0, c1 = 0, c2 = 0, c3 = 0;
    #pragma unroll
    for (int i = 0; i < 32; i++) {
        unsigned char s = g_sel[t0 + i]; sel[i] = s;
        if (s == 0) c0++; else if (s == 1) c1++; else if (s == 2) c2++; else c3++;
    }
    scnt[tid] = c0; scnt[1024 + tid] = c1; scnt[2048 + tid] = c2; scnt[3072 + tid] = c3;
    __syncthreads();
    if (tid < NM * 32) {
        int m = tid >> 5, lane = tid & 31;
        int* a = &scnt[m * 1024 + lane * 32];
        int s = 0;
        #pragma unroll
        for (int k = 0; k < 32; k++) s += a[k];
        int incl = s;
        #pragma unroll
        for (int d = 1; d < 32; d <<= 1) {
            int v = __shfl_up_sync(0xffffffffu, incl, d);
            if (lane >= d) incl += v;
        }
        int run = incl - s;
        #pragma unroll
        for (int k = 0; k < 32; k++) { int v = a[k]; a[k] = run; run += v; }
        if (lane == 31) g_cnt[m] = incl;
    }
    __syncthreads();
    int o0 = scnt[tid], o1 = scnt[1024 + tid], o2 = scnt[2048 + tid], o3 = scnt[3072 + tid];
    #pragma unroll
    for (int i = 0; i < 32; i++) {
        int t = t0 + i; unsigned char s = sel[i];
        if (s == 0) g_list[o0++] = t;
        else if (s == 1) g_list[NTOK + o1++] = t;
        else if (s == 2) g_list[2 * NTOK + o2++] = t;
        else g_list[3 * NTOK + o3++] = t;
    }
}

// gates chunk (16 K-rows) for one warp: 1 mt x 4 nt, accumulate r, z, one of {n, hn}
__device__ __forceinline__ void do_gates(
    const float* __restrict__ Ar, int stride, int col0,
    const float4* __restrict__ Bp, int wt, int wcg, int ql, int qc, int l,
    float (&gR)[4][4], float (&gZ)[4][4], float (&gNx)[4][4])
{
    uint32_t a[2][4];
    #pragma unroll
    for (int ks = 0; ks < 2; ks++) {
        const float* Ab = Ar + (16 * wt + ql) * stride + col0 + 8 * ks + qc;
        a[ks][0] = __float_as_uint(Ab[0]);
        a[ks][1] = __float_as_uint(Ab[8 * stride]);
        a[ks][2] = __float_as_uint(Ab[4]);
        a[ks][3] = __float_as_uint(Ab[8 * stride + 4]);
    }
    #pragma unroll
    for (int j = 0; j < 4; j++) {
        float4 b = Bp[(4 * wcg + j) * 32 + l];
        mma8(gR[j], a[0], __float_as_uint(b.x), __float_as_uint(b.y));
        mma8(gR[j], a[1], __float_as_uint(b.z), __float_as_uint(b.w));
    }
    #pragma unroll
    for (int j = 0; j < 4; j++) {
        float4 b = Bp[(16 + 4 * wcg + j) * 32 + l];
        mma8(gZ[j], a[0], __float_as_uint(b.x), __float_as_uint(b.y));
        mma8(gZ[j], a[1], __float_as_uint(b.z), __float_as_uint(b.w));
    }
    #pragma unroll
    for (int j = 0; j < 4; j++) {
        float4 b = Bp[(32 + 4 * wcg + j) * 32 + l];
        mma8(gNx[j], a[0], __float_as_uint(b.x), __float_as_uint(b.y));
        mma8(gNx[j], a[1], __float_as_uint(b.z), __float_as_uint(b.w));
    }
}

// ---------------- main: mma.sync tf32, 512 threads / 16 warps ----------------
__global__ void __launch_bounds__(512, 1) main_kernel(
    const float* __restrict__ x_in, const float* __restrict__ hidden,
    const float* __restrict__ fc1b,
    const float* __restrict__ bih, const float* __restrict__ bhh,
    const float* __restrict__ fc2w, const float* __restrict__ fc2b,
    float* __restrict__ out_q, float* __restrict__ out_h)
{
    extern __shared__ float S[];
    const int m = blockIdx.y;
    const int cnt = g_cnt[m];
    const int base = blockIdx.x * TT;
    if (base >= cnt) return;
    const int nvalid = min(TT, cnt - base);
    const int tid = threadIdx.x, w = tid >> 5, l = tid & 31;
    const int ql = l >> 2, qc = l & 3;
    const int wt = w & 3, wcg = w >> 2;       // warp = (mt tile, 32-col group)

    int* sidx = (int*)(S + OFF_AUX);
    if (tid < TT) sidx[tid] = g_list[m * NTOK + min(base + tid, cnt - 1)];
    { int t = tid >> 3, c = 204 + (tid & 7); S[OFF_X + t * SX + c] = 0.f; }
    __syncthreads();

    const uint32_t sb = smem_u32(S);
    for (int i = tid; i < TT * 51; i += 512) {
        int t = i / 51, c = i - t * 51;
        cpa16(sb + (uint32_t)(OFF_X + t * SX + c * 4) * 4,
              x_in + (size_t)sidx[t] * INF + c * 4);
    }
    for (int i = tid; i < TT * 32; i += 512) {
        int t = i >> 5, c = i & 31;
        cpa16(sb + (uint32_t)(OFF_H + t * SH + c * 4) * 4,
              hidden + (size_t)sidx[t] * HD + c * 4);
    }
    if (tid < 448) cpa16(sb + (uint32_t)(OFF_W2) * 4 + tid * 16,
                         fc2w + (size_t)m * HD * AD + tid * 4);
    cpa_commit();
    const float* stream = g_S + (size_t)m * STREAM_F;
    for (int q = tid; q < 1536; q += 512)
        cpa16(sb + (uint32_t)(OFF_STG) * 4 + q * 16, stream + q * 4);
    cpa_commit();
    for (int q = tid; q < 1536; q += 512)
        cpa16(sb + (uint32_t)(OFF_STG + CH_F) * 4 + q * 16, stream + CH_F + q * 4);
    cpa_commit();

    // gR doubles as the fc1 accumulator (re-zeroed at the fc1 epilogue)
    float gR[4][4], gZ[4][4], gN[4][4], gHn[4][4];
    #pragma unroll
    for (int j = 0; j < 4; j++)
        #pragma unroll
        for (int s = 0; s < 4; s++) { gR[j][s]=0.f; gZ[j][s]=0.f; gN[j][s]=0.f; gHn[j][s]=0.f; }

    for (int i = 0; i < NCH; i++) {
        if (i == NCH - 1) cpa_wait<0>(); else cpa_wait<1>();
        __syncthreads();
        if (i + 2 < NCH) {
            const float* src = stream + (size_t)(i + 2) * CH_F;
            const uint32_t dst = sb + (uint32_t)(OFF_STG + ((i + 2) % 3) * CH_F) * 4;
            for (int q = tid; q < 1536; q += 512) cpa16(dst + q * 16, src + q * 4);
            cpa_commit();
        }
        const float4* Bp = (const float4*)(S + OFF_STG + (i % 3) * CH_F);

        if (i < 5) {
            // fc1 into gR: 48 K-rows; warp owns mt=wt, ntiles 4*wcg..+3
            #pragma unroll
            for (int p = 0; p < 3; p++) {
                const int col0 = 48 * i + 16 * p;
                uint32_t a[2][4];
                #pragma unroll
                for (int ks = 0; ks < 2; ks++) {
                    const float* Ab = S + OFF_X + (16 * wt + ql) * SX + col0 + 8 * ks + qc;
                    a[ks][0] = __float_as_uint(Ab[0]);
                    a[ks][1] = __float_as_uint(Ab[8 * SX]);
                    a[ks][2] = __float_as_uint(Ab[4]);
                    a[ks][3] = __float_as_uint(Ab[8 * SX + 4]);
                }
                #pragma unroll
                for (int j = 0; j < 4; j++) {
                    float4 b = Bp[((4 * wcg + j) * 3 + p) * 32 + l];
                    mma8(gR[j], a[0], __float_as_uint(b.x), __float_as_uint(b.y));
                    mma8(gR[j], a[1], __float_as_uint(b.z), __float_as_uint(b.w));
                }
            }
            if (i == 4) {
                // relu + bias -> XA (cols 0..127 of X region); then re-zero gR for gates
                #pragma unroll
                for (int j = 0; j < 4; j++) {
                    #pragma unroll
                    for (int s = 0; s < 4; s++) {
                        int row = 16 * wt + ql + ((s >> 1) << 3);
                        int col = 32 * wcg + 8 * j + 2 * qc + (s & 1);
                        S[OFF_X + row * SX + col] =
                            fmaxf(gR[j][s] + __ldg(fc1b + m * HD + col), 0.f);
                        gR[j][s] = 0.f;
                    }
                }
            }
        } else {
            const int c = i - 5;
            if (c < 8) do_gates(S + OFF_X, SX, 16 * c, Bp, wt, wcg, ql, qc, l, gR, gZ, gN);
            else       do_gates(S + OFF_H, SH, 16 * c - 128, Bp, wt, wcg, ql, qc, l, gR, gZ, gHn);
        }
    }

    // GRU elementwise in registers; h_new -> H region
    {
        const float* bi = bih + (size_t)m * 384;
        const float* bh = bhh + (size_t)m * 384;
        #pragma unroll
        for (int j = 0; j < 4; j++) {
            #pragma unroll
            for (int p = 0; p < 2; p++) {
                const int cb = 32 * wcg + 8 * j + 2 * qc + p;
                const float br  = __ldg(bi + cb) + __ldg(bh + cb);
                const float bz  = __ldg(bi + 128 + cb) + __ldg(bh + 128 + cb);
                const float bin = __ldg(bi + 256 + cb);
                const float bhn = __ldg(bh + 256 + cb);
                #pragma unroll
                for (int half = 0; half < 2; half++) {
                    const int s = half * 2 + p;
                    const int row = 16 * wt + ql + half * 8;
                    float r  = sigf(gR[j][s] + br);
                    float z  = sigf(gZ[j][s] + bz);
                    float ng = tanhfast(gN[j][s] + bin + r * (gHn[j][s] + bhn));
                    float h0 = S[OFF_H + row * SH + cb];
                    S[OFF_H + row * SH + cb] = fmaf(z, h0 - ng, ng);
                }
            }
        }
    }
    __syncthreads();

    // out_h (coalesced vec4)
    for (int i = tid; i < TT * 32; i += 512) {
        int t = i >> 5, g = i & 31;
        if (t < nvalid)
            *(float4*)(out_h + (size_t)sidx[t] * HD + g * 4) =
                *(float4*)(S + OFF_H + t * SH + g * 4);
    }

    // fc2: q = h_new @ W2 + b2 (8 threads/token)
    {
        const float* Sw = S + OFF_W2;
        const int t = tid >> 3, rep = tid & 7;
        const float* hrow = S + OFF_H + t * SH;
        float a0 = 0.f, a1 = 0.f;
        for (int k = 0; k < HD; k++) {
            float hv = hrow[k];
            a0 = fmaf(hv, Sw[k * AD + rep], a0);
            if (rep < 6) a1 = fmaf(hv, Sw[k * AD + rep + 8], a1);
        }
        if (t < nvalid) {
            const float* b2p = fc2b + (size_t)m * AD;
            size_t o = (size_t)sidx[t] * AD;
            out_q[o + rep] = a0 + __ldg(b2p + rep);
            if (rep < 6) out_q[o + rep + 8] = a1 + __ldg(b2p + rep + 8);
        }
    }
}

extern "C" void kernel_launch(void* const* d_in, const int* in_sizes, int n_in,
                              void* d_out, int out_size) {
    const float* x    = (const float*)d_in[0];
    const float* h    = (const float*)d_in[1];
    const float* fc1w = (const float*)d_in[2];
    const float* fc1b = (const float*)d_in[3];
    const float* wih  = (const float*)d_in[4];
    const float* whh  = (const float*)d_in[5];
    const float* bih  = (const float*)d_in[6];
    const float* bhh  = (const float*)d_in[7];
    const float* fc2w = (const float*)d_in[8];
    const float* fc2b = (const float*)d_in[9];
    const float* w1   = (const float*)d_in[10];
    const float* b1   = (const float*)d_in[11];
    const float* w2   = (const float*)d_in[12];
    const float* b2   = (const float*)d_in[13];
    const float* w3   = (const float*)d_in[14];
    const float* b3   = (const float*)d_in[15];
    const float* mk   = (const float*)d_in[16];
    const float* wq   = (const float*)d_in[17];
    const float* bq   = (const float*)d_in[18];
    const float* wk   = (const float*)d_in[19];
    const float* bk   = (const float*)d_in[20];
    const float* un   = (const float*)d_in[21];

    float* outq = (float*)d_out;
    float* outh = outq + (size_t)NTOK * AD;

    cudaFuncSetAttribute(main_kernel, cudaFuncAttributeMaxDynamicSharedMemorySize, SMEM_MAIN_BYTES);
    cudaFuncSetAttribute(router_prep_kernel, cudaFuncAttributeMaxDynamicSharedMemorySize, SMEM_ROUTER);

    router_prep_kernel<<<256 + NM * NCH, 256, SMEM_ROUTER>>>(
        h, w1, b1, w2, b2, w3, b3, wq, bq, wk, bk, mk, un, wih, whh, fc1w);
    compact_kernel<<<1, 1024>>>();
    main_kernel<<<dim3(NTOK / TT, NM), 512, SMEM_MAIN_BYTES>>>(x, h, fc1b, bih, bhh,
                                                               fc2w, fc2b, outq, outh);
}